// round 3
// baseline (speedup 1.0000x reference)
#include <cuda_runtime.h>

#define NN 100000
#define EE 1000000
#define GG 2000

// ---------------- scratch (device globals; no allocation allowed) ----------
__device__ float g_buf0[NN * 64];
__device__ float g_buf1[NN * 64];
__device__ int   g_rowptr[NN + 1];
__device__ int   g_cnt[NN];
__device__ int   g_cursor[NN];
__device__ int   g_srcperm[EE];
__device__ int   g_eid[EE];
__device__ float g_eaperm[EE * 16];
__device__ float g_sums[GG * 64];
__device__ float g_cnts[GG];

typedef unsigned long long ull;

__device__ __forceinline__ ull pack2(float a, float b) {
    ull r; asm("mov.b64 %0, {%1,%2};" : "=l"(r) : "f"(a), "f"(b)); return r;
}
__device__ __forceinline__ void unpack2(ull v, float& a, float& b) {
    asm("mov.b64 {%0,%1}, %2;" : "=f"(a), "=f"(b) : "l"(v));
}
__device__ __forceinline__ void ffma2(ull& d, ull a, ull b) {
    asm("fma.rn.f32x2 %0, %1, %2, %0;" : "+l"(d) : "l"(a), "l"(b));
}
__device__ __forceinline__ ull add2(ull a, ull b) {
    ull r; asm("add.rn.f32x2 %0, %1, %2;" : "=l"(r) : "l"(a), "l"(b)); return r;
}
__device__ __forceinline__ void red2(float* p, float x, float y) {
    asm volatile("red.global.add.v2.f32 [%0], {%1,%2};"
                 :: "l"(p), "f"(x), "f"(y) : "memory");
}

// ============================ CSR build =====================================
__global__ void __launch_bounds__(256) count_kernel(const int* __restrict__ ei,
                                                    int* __restrict__ cnt) {
    int e = blockIdx.x * blockDim.x + threadIdx.x;
    if (e < EE) atomicAdd(&cnt[ei[EE + e]], 1);
}

// Single-block exclusive scan over NN counts -> rowptr[NN+1], also cursor.
__global__ void __launch_bounds__(1024) scan_kernel(const int* __restrict__ cnt,
                                                    int* __restrict__ rowptr,
                                                    int* __restrict__ cursor) {
    const int CH = 100;  // 1024*100 >= NN+1
    int tid = threadIdx.x;
    int base = tid * CH;
    int s = 0;
    // vectorized partial sum (cnt is int[NN], NN % 4 == 0, base % 4 == 0)
    for (int i = 0; i < CH; i += 4) {
        int idx = base + i;
        if (idx + 3 < NN) {
            int4 v = *(const int4*)(cnt + idx);
            s += v.x + v.y + v.z + v.w;
        } else {
            for (int t = 0; t < 4; t++)
                if (idx + t < NN) s += cnt[idx + t];
        }
    }
    __shared__ int sh[1024];
    sh[tid] = s;
    __syncthreads();
    for (int off = 1; off < 1024; off <<= 1) {
        int v = (tid >= off) ? sh[tid - off] : 0;
        __syncthreads();
        sh[tid] += v;
        __syncthreads();
    }
    int run = sh[tid] - s;  // exclusive prefix of this chunk
    for (int i = 0; i < CH; i++) {
        int idx = base + i;
        if (idx < NN) {
            rowptr[idx] = run;
            cursor[idx] = run;
            run += cnt[idx];
        }
    }
    if (NN >= base && NN < base + CH) rowptr[NN] = run;
}

__global__ void __launch_bounds__(256) scatter_kernel(const int* __restrict__ ei,
                                                      int* __restrict__ cursor,
                                                      int* __restrict__ srcperm,
                                                      int* __restrict__ eid) {
    int e = blockIdx.x * blockDim.x + threadIdx.x;
    if (e < EE) {
        int d = ei[EE + e];
        int pos = atomicAdd(&cursor[d], 1);
        srcperm[pos] = ei[e];
        eid[pos] = e;
    }
}

__global__ void __launch_bounds__(256) permute_ea_kernel(const float* __restrict__ ea,
                                                         const int* __restrict__ eid,
                                                         float* __restrict__ eaperm) {
    int idx = blockIdx.x * blockDim.x + threadIdx.x;  // over EE*4 float4 chunks
    if (idx < EE * 4) {
        int j = idx >> 2, c = idx & 3;
        ((float4*)eaperm)[(size_t)j * 4 + c] =
            ((const float4*)ea)[(size_t)eid[j] * 4 + c];
    }
}

// ============================ fused layer ===================================
// Lane owns dims (2*lane, 2*lane+1) packed f32x2. Warp handles 4 nodes with a
// single flattened, pipelined edge loop over CSR range [rowptr[n0], rowptr[n0+4]).
template <bool LAST>
__global__ void __launch_bounds__(256, 4) layer_kernel(
    const float* __restrict__ x,
    const int* __restrict__ rowptr, const int* __restrict__ srcperm,
    const float* __restrict__ eaperm,
    const float* __restrict__ line,
    const float* __restrict__ W1, const float* __restrict__ b1,
    const float* __restrict__ W2, const float* __restrict__ b2,
    const float* __restrict__ epsp, int l,
    float* __restrict__ xout,
    const int* __restrict__ batch,
    float* __restrict__ sums, float* __restrict__ cnts)
{
    __shared__ ull W1s[64 * 32];
    __shared__ ull W2s[64 * 32];
    __shared__ ull h_sh[8][4][32];
    for (int i = threadIdx.x; i < 64 * 32; i += 256) {
        int k = i >> 5, d2 = (i & 31) * 2;
        W1s[i] = pack2(W1[k * 64 + d2], W1[k * 64 + d2 + 1]);
        W2s[i] = pack2(W2[k * 64 + d2], W2[k * 64 + d2 + 1]);
    }
    __syncthreads();

    const int lane = threadIdx.x & 31;
    const int wib  = threadIdx.x >> 5;

    // Edge-transform weights in registers: lin_e[k][2*lane .. +1], k=0..15
    ull w[16];
#pragma unroll
    for (int k = 0; k < 16; k++) {
        float2 wv = *(const float2*)(line + k * 64 + lane * 2);
        w[k] = pack2(wv.x, wv.y);
    }

    const float epsv = 1.0f + epsp[l];

    const int warp = (blockIdx.x * 256 + threadIdx.x) >> 5;
    const int n0 = warp * 4;  // grid sized exactly: n0+3 <= NN-1

    const int b0 = rowptr[n0];
    const int r1 = rowptr[n0 + 1];
    const int r2 = rowptr[n0 + 2];
    const int r3 = rowptr[n0 + 3];
    const int r4 = rowptr[n0 + 4];

    // ---- flattened, pipelined edge phase ----
    {
        int j = 0;
        int bnext = r1;
        float a0 = 0.f, a1 = 0.f;
        int p = b0;
        int s_next = (p < r4) ? __ldg(srcperm + p) : 0;

        while (p < r4) {
            // flush completed segments
            while (p >= bnext) {
                float2 xs = *(const float2*)(x + (size_t)(n0 + j) * 64 + lane * 2);
                h_sh[wib][j][lane] = pack2(fmaf(epsv, xs.x, a0), fmaf(epsv, xs.y, a1));
                a0 = 0.f; a1 = 0.f;
                j++;
                bnext = (j == 1) ? r2 : (j == 2) ? r3 : r4;
            }
            int s = s_next;
            if (p + 1 < r4) s_next = __ldg(srcperm + p + 1);
            float2 xv = __ldg((const float2*)(x + (size_t)s * 64 + lane * 2));

            const float4* eap = (const float4*)(eaperm + (size_t)p * 16);
            float4 q0 = __ldcs(eap + 0);
            float4 q1 = __ldcs(eap + 1);
            float4 q2 = __ldcs(eap + 2);
            float4 q3 = __ldcs(eap + 3);

            ull eA = pack2(0.f, 0.f);
            ull eB = pack2(0.f, 0.f);
            ffma2(eA, pack2(q0.x, q0.x), w[0]);
            ffma2(eB, pack2(q0.y, q0.y), w[1]);
            ffma2(eA, pack2(q0.z, q0.z), w[2]);
            ffma2(eB, pack2(q0.w, q0.w), w[3]);
            ffma2(eA, pack2(q1.x, q1.x), w[4]);
            ffma2(eB, pack2(q1.y, q1.y), w[5]);
            ffma2(eA, pack2(q1.z, q1.z), w[6]);
            ffma2(eB, pack2(q1.w, q1.w), w[7]);
            ffma2(eA, pack2(q2.x, q2.x), w[8]);
            ffma2(eB, pack2(q2.y, q2.y), w[9]);
            ffma2(eA, pack2(q2.z, q2.z), w[10]);
            ffma2(eB, pack2(q2.w, q2.w), w[11]);
            ffma2(eA, pack2(q3.x, q3.x), w[12]);
            ffma2(eB, pack2(q3.y, q3.y), w[13]);
            ffma2(eA, pack2(q3.z, q3.z), w[14]);
            ffma2(eB, pack2(q3.w, q3.w), w[15]);
            ull es = add2(eA, eB);
            float m0, m1;
            unpack2(es, m0, m1);
            a0 += fmaxf(m0 + xv.x, 0.f);   // gathered x enters late: latency overlapped
            a1 += fmaxf(m1 + xv.y, 0.f);
            p++;
        }
        // flush remaining segments (including zero-degree nodes)
        while (j < 4) {
            float2 xs = *(const float2*)(x + (size_t)(n0 + j) * 64 + lane * 2);
            h_sh[wib][j][lane] = pack2(fmaf(epsv, xs.x, a0), fmaf(epsv, xs.y, a1));
            a0 = 0.f; a1 = 0.f;
            j++;
        }
    }
    __syncwarp();

    float h0[4], h1[4];
#pragma unroll
    for (int j = 0; j < 4; j++) unpack2(h_sh[wib][j][lane], h0[j], h1[j]);

    const ull b1p = pack2(b1[lane * 2], b1[lane * 2 + 1]);
    const ull b2p = pack2(b2[lane * 2], b2[lane * 2 + 1]);

    // ---- MLP matmul 1 ----
    ull acc[4] = {b1p, b1p, b1p, b1p};
#pragma unroll 8
    for (int kk = 0; kk < 32; kk++) {
        ull wa = W1s[(2 * kk) * 32 + lane];
        ull wb = W1s[(2 * kk + 1) * 32 + lane];
#pragma unroll
        for (int j = 0; j < 4; j++) {
            float a = __shfl_sync(0xFFFFFFFFu, h0[j], kk);
            float b = __shfl_sync(0xFFFFFFFFu, h1[j], kk);
            ffma2(acc[j], pack2(a, a), wa);
            ffma2(acc[j], pack2(b, b), wb);
        }
    }
#pragma unroll
    for (int j = 0; j < 4; j++) {
        float y0, y1;
        unpack2(acc[j], y0, y1);
        h0[j] = fmaxf(y0, 0.f);
        h1[j] = fmaxf(y1, 0.f);
        acc[j] = b2p;
    }

    // ---- MLP matmul 2 ----
#pragma unroll 8
    for (int kk = 0; kk < 32; kk++) {
        ull wa = W2s[(2 * kk) * 32 + lane];
        ull wb = W2s[(2 * kk + 1) * 32 + lane];
#pragma unroll
        for (int j = 0; j < 4; j++) {
            float a = __shfl_sync(0xFFFFFFFFu, h0[j], kk);
            float b = __shfl_sync(0xFFFFFFFFu, h1[j], kk);
            ffma2(acc[j], pack2(a, a), wa);
            ffma2(acc[j], pack2(b, b), wb);
        }
    }

#pragma unroll
    for (int j = 0; j < 4; j++) {
        float y0, y1;
        unpack2(acc[j], y0, y1);
        y0 = fmaxf(y0, 0.f);
        y1 = fmaxf(y1, 0.f);
        if (!LAST) {
            *(float2*)(xout + (size_t)(n0 + j) * 64 + lane * 2) = make_float2(y0, y1);
        } else {
            int g = batch[n0 + j];
            red2(sums + (size_t)g * 64 + lane * 2, y0, y1);
            if (lane == 0) atomicAdd(cnts + g, 1.0f);
        }
    }
}

// ============================ head ==========================================
__global__ void __launch_bounds__(256) head_kernel(
    const float* __restrict__ sums, const float* __restrict__ cnts,
    const float* __restrict__ t_cond,
    const float* __restrict__ hW1, const float* __restrict__ hb1,
    const float* __restrict__ hW2, const float* __restrict__ hb2,
    float* __restrict__ out)
{
    const int lane = threadIdx.x & 31;
    const int g    = (blockIdx.x * blockDim.x + threadIdx.x) >> 5;
    if (g >= GG) return;

    float c  = fmaxf(cnts[g], 1.0f);
    float p0 = sums[(size_t)g * 64 + lane] / c;
    float p1 = sums[(size_t)g * 64 + lane + 32] / c;

    float acc0 = hb1[lane], acc1 = hb1[lane + 32];
    for (int k = 0; k < 32; k++) {
        float a = __shfl_sync(0xFFFFFFFFu, p0, k);
        acc0 = fmaf(a, hW1[k * 64 + lane],      acc0);
        acc1 = fmaf(a, hW1[k * 64 + lane + 32], acc1);
    }
    for (int k = 0; k < 32; k++) {
        float a = __shfl_sync(0xFFFFFFFFu, p1, k);
        acc0 = fmaf(a, hW1[(k + 32) * 64 + lane],      acc0);
        acc1 = fmaf(a, hW1[(k + 32) * 64 + lane + 32], acc1);
    }
    float t = t_cond[g];
    acc0 = fmaf(t, hW1[64 * 64 + lane],      acc0);
    acc1 = fmaf(t, hW1[64 * 64 + lane + 32], acc1);

    acc0 = fmaxf(acc0, 0.f);
    acc1 = fmaxf(acc1, 0.f);

    float r = acc0 * hW2[lane] + acc1 * hW2[lane + 32];
#pragma unroll
    for (int o = 16; o; o >>= 1) r += __shfl_xor_sync(0xFFFFFFFFu, r, o);
    if (lane == 0) out[g] = r + hb2[0];
}

// ============================================================================
extern "C" void kernel_launch(void* const* d_in, const int* in_sizes, int n_in,
                              void* d_out, int out_size)
{
    const float* x      = (const float*)d_in[0];
    const int*   ei     = (const int*)  d_in[1];
    const float* ea     = (const float*)d_in[2];
    const int*   batch  = (const int*)  d_in[3];
    const float* t_cond = (const float*)d_in[4];
    const float* lin_e  = (const float*)d_in[5];
    const float* W1     = (const float*)d_in[6];
    const float* b1     = (const float*)d_in[7];
    const float* W2     = (const float*)d_in[8];
    const float* b2     = (const float*)d_in[9];
    const float* eps    = (const float*)d_in[10];
    const float* hW1    = (const float*)d_in[11];
    const float* hb1    = (const float*)d_in[12];
    const float* hW2    = (const float*)d_in[13];
    const float* hb2    = (const float*)d_in[14];
    float* out = (float*)d_out;

    float *buf0, *buf1, *eaperm, *sums, *cnts;
    int *rowptr, *cnt, *cursor, *srcperm, *eid;
    cudaGetSymbolAddress((void**)&buf0, g_buf0);
    cudaGetSymbolAddress((void**)&buf1, g_buf1);
    cudaGetSymbolAddress((void**)&rowptr, g_rowptr);
    cudaGetSymbolAddress((void**)&cnt, g_cnt);
    cudaGetSymbolAddress((void**)&cursor, g_cursor);
    cudaGetSymbolAddress((void**)&srcperm, g_srcperm);
    cudaGetSymbolAddress((void**)&eid, g_eid);
    cudaGetSymbolAddress((void**)&eaperm, g_eaperm);
    cudaGetSymbolAddress((void**)&sums, g_sums);
    cudaGetSymbolAddress((void**)&cnts, g_cnts);

    // ---- CSR build: launches 1..5, so ncu (-s 5) captures layer 1 next ----
    cudaMemsetAsync(cnt, 0, sizeof(int) * NN, 0);                       // 1
    count_kernel<<<(EE + 255) / 256, 256>>>(ei, cnt);                   // 2
    scan_kernel<<<1, 1024>>>(cnt, rowptr, cursor);                      // 3
    scatter_kernel<<<(EE + 255) / 256, 256>>>(ei, cursor, srcperm, eid);// 4
    permute_ea_kernel<<<(EE * 4 + 255) / 256, 256>>>(ea, eid, eaperm);  // 5

    // ---- 4 fused layers ----
    const int blocks = NN / 4 / 8;  // 3125: 4 nodes/warp, 8 warps/block
    float* bufs[2] = {buf0, buf1};
    const float* cur = x;
    for (int l = 0; l < 3; l++) {
        float* nxt = bufs[l & 1];
        layer_kernel<false><<<blocks, 256>>>(
            cur, rowptr, srcperm, eaperm,
            lin_e + (size_t)l * 16 * 64,
            W1 + (size_t)l * 64 * 64, b1 + (size_t)l * 64,
            W2 + (size_t)l * 64 * 64, b2 + (size_t)l * 64,
            eps, l, nxt, batch, sums, cnts);
        cur = nxt;
    }
    cudaMemsetAsync(sums, 0, sizeof(float) * GG * 64, 0);
    cudaMemsetAsync(cnts, 0, sizeof(float) * GG, 0);
    layer_kernel<true><<<blocks, 256>>>(
        cur, rowptr, srcperm, eaperm,
        lin_e + (size_t)3 * 16 * 64,
        W1 + (size_t)3 * 64 * 64, b1 + (size_t)3 * 64,
        W2 + (size_t)3 * 64 * 64, b2 + (size_t)3 * 64,
        eps, 3, nullptr, batch, sums, cnts);

    head_kernel<<<(GG + 7) / 8, 256>>>(sums, cnts, t_cond, hW1, hb1, hW2, hb2, out);
}

// round 4
// speedup vs baseline: 1.0357x; 1.0357x over previous
#include <cuda_runtime.h>

#define NN 100000
#define EE 1000000
#define GG 2000

// ---------------- scratch (device globals; no allocation allowed) ----------
__device__ float g_buf0[NN * 64];
__device__ float g_buf1[NN * 64];
__device__ int   g_rowptr[NN + 1];
__device__ int   g_cnt[NN];       // zero-init at load; cleanup re-zeros
__device__ int   g_cursor[NN];
__device__ int   g_srcperm[EE];
__device__ float g_eaperm[EE * 16];
__device__ float g_sums[GG * 64]; // zero-init at load; cleanup re-zeros
__device__ float g_cnts[GG];      // zero-init at load; cleanup re-zeros

typedef unsigned long long ull;

__device__ __forceinline__ ull pack2(float a, float b) {
    ull r; asm("mov.b64 %0, {%1,%2};" : "=l"(r) : "f"(a), "f"(b)); return r;
}
__device__ __forceinline__ void unpack2(ull v, float& a, float& b) {
    asm("mov.b64 {%0,%1}, %2;" : "=f"(a), "=f"(b) : "l"(v));
}
__device__ __forceinline__ void ffma2(ull& d, ull a, ull b) {
    asm("fma.rn.f32x2 %0, %1, %2, %0;" : "+l"(d) : "l"(a), "l"(b));
}
__device__ __forceinline__ ull add2(ull a, ull b) {
    ull r; asm("add.rn.f32x2 %0, %1, %2;" : "=l"(r) : "l"(a), "l"(b)); return r;
}
__device__ __forceinline__ void red2(float* p, float x, float y) {
    asm volatile("red.global.add.v2.f32 [%0], {%1,%2};"
                 :: "l"(p), "f"(x), "f"(y) : "memory");
}

// ============================ CSR build =====================================
__global__ void __launch_bounds__(256) count_kernel(const int* __restrict__ ei,
                                                    int* __restrict__ cnt) {
    int e = blockIdx.x * blockDim.x + threadIdx.x;
    if (e < EE) atomicAdd(&cnt[ei[EE + e]], 1);
}

// Single-block exclusive scan over NN counts -> rowptr[NN+1] and cursor.
__global__ void __launch_bounds__(1024) scan_kernel(const int* __restrict__ cnt,
                                                    int* __restrict__ rowptr,
                                                    int* __restrict__ cursor) {
    const int CH = 100;
    int tid = threadIdx.x;
    int base = tid * CH;
    int s = 0;
    for (int i = 0; i < CH; i += 4) {
        int idx = base + i;
        if (idx + 3 < NN) {
            int4 v = *(const int4*)(cnt + idx);
            s += v.x + v.y + v.z + v.w;
        } else {
            for (int t = 0; t < 4; t++)
                if (idx + t < NN) s += cnt[idx + t];
        }
    }
    __shared__ int sh[1024];
    sh[tid] = s;
    __syncthreads();
    for (int off = 1; off < 1024; off <<= 1) {
        int v = (tid >= off) ? sh[tid - off] : 0;
        __syncthreads();
        sh[tid] += v;
        __syncthreads();
    }
    int run = sh[tid] - s;
    for (int i = 0; i < CH; i++) {
        int idx = base + i;
        if (idx < NN) {
            rowptr[idx] = run;
            cursor[idx] = run;
            run += cnt[idx];
        }
    }
    if (NN >= base && NN < base + CH) rowptr[NN] = run;
}

// Scatter + edge_attr permute fused: thread e writes srcperm[pos] and copies
// its 64B edge_attr row to eaperm[pos].
__global__ void __launch_bounds__(256) scatter_kernel(const int* __restrict__ ei,
                                                      const float* __restrict__ ea,
                                                      int* __restrict__ cursor,
                                                      int* __restrict__ srcperm,
                                                      float* __restrict__ eaperm) {
    int e = blockIdx.x * blockDim.x + threadIdx.x;
    if (e < EE) {
        int d = ei[EE + e];
        int pos = atomicAdd(&cursor[d], 1);
        srcperm[pos] = ei[e];
        const float4* src = (const float4*)(ea + (size_t)e * 16);
        float4* dst = (float4*)(eaperm + (size_t)pos * 16);
        float4 v0 = src[0], v1 = src[1], v2 = src[2], v3 = src[3];
        dst[0] = v0; dst[1] = v1; dst[2] = v2; dst[3] = v3;
    }
}

// ============================ fused layer ===================================
// Lane owns dims (2*lane, 2*lane+1). Warp handles 4 nodes.
// MLP uses pre-duplicated activations in shared + LDS.128 vector loads.
template <bool LAST>
__global__ void __launch_bounds__(256) layer_kernel(
    const float* __restrict__ x,
    const int* __restrict__ rowptr, const int* __restrict__ srcperm,
    const float* __restrict__ eaperm,
    const float* __restrict__ line,
    const float* __restrict__ W1, const float* __restrict__ b1,
    const float* __restrict__ W2, const float* __restrict__ b2,
    const float* __restrict__ epsp, int l,
    float* __restrict__ xout,
    const int* __restrict__ batch,
    float* __restrict__ sums, float* __restrict__ cnts)
{
    // Weight layout: Wv[kk][lane] = { (W[2kk][2l],W[2kk][2l+1]), (W[2kk+1][2l],W[2kk+1][2l+1]) }
    __shared__ ulonglong2 W1v[32 * 32];
    __shared__ ulonglong2 W2v[32 * 32];
    __shared__ ull hdup[8][4][64];   // per-warp duplicated activations
    for (int i = threadIdx.x; i < 32 * 32; i += 256) {
        int kk = i >> 5, ln = i & 31;
        W1v[i] = make_ulonglong2(
            pack2(W1[(2 * kk) * 64 + 2 * ln],     W1[(2 * kk) * 64 + 2 * ln + 1]),
            pack2(W1[(2 * kk + 1) * 64 + 2 * ln], W1[(2 * kk + 1) * 64 + 2 * ln + 1]));
        W2v[i] = make_ulonglong2(
            pack2(W2[(2 * kk) * 64 + 2 * ln],     W2[(2 * kk) * 64 + 2 * ln + 1]),
            pack2(W2[(2 * kk + 1) * 64 + 2 * ln], W2[(2 * kk + 1) * 64 + 2 * ln + 1]));
    }
    __syncthreads();

    const int lane = threadIdx.x & 31;
    const int wib  = threadIdx.x >> 5;

    // Edge-transform weights in registers: lin_e[k][2*lane .. +1], k=0..15
    ull w[16];
#pragma unroll
    for (int k = 0; k < 16; k++) {
        float2 wv = *(const float2*)(line + k * 64 + lane * 2);
        w[k] = pack2(wv.x, wv.y);
    }

    const float epsv = 1.0f + epsp[l];
    const int warp = (blockIdx.x * 256 + threadIdx.x) >> 5;
    const int n0 = warp * 4;  // grid sized exactly

    // ---- edge phase (R2-proven structure) ----
#pragma unroll
    for (int j = 0; j < 4; j++) {
        const int n = n0 + j;
        float a0 = 0.f, a1 = 0.f;
        const int p0 = rowptr[n], p1 = rowptr[n + 1];
#pragma unroll 2
        for (int p = p0; p < p1; p++) {
            int s = __ldg(srcperm + p);
            float2 xv = __ldg((const float2*)(x + (size_t)s * 64 + lane * 2));
            const float4* eap = (const float4*)(eaperm + (size_t)p * 16);
            float4 q0 = __ldg(eap + 0);
            float4 q1 = __ldg(eap + 1);
            float4 q2 = __ldg(eap + 2);
            float4 q3 = __ldg(eap + 3);
            ull eA = pack2(xv.x, xv.y);
            ull eB = pack2(0.f, 0.f);
            ffma2(eA, pack2(q0.x, q0.x), w[0]);
            ffma2(eB, pack2(q0.y, q0.y), w[1]);
            ffma2(eA, pack2(q0.z, q0.z), w[2]);
            ffma2(eB, pack2(q0.w, q0.w), w[3]);
            ffma2(eA, pack2(q1.x, q1.x), w[4]);
            ffma2(eB, pack2(q1.y, q1.y), w[5]);
            ffma2(eA, pack2(q1.z, q1.z), w[6]);
            ffma2(eB, pack2(q1.w, q1.w), w[7]);
            ffma2(eA, pack2(q2.x, q2.x), w[8]);
            ffma2(eB, pack2(q2.y, q2.y), w[9]);
            ffma2(eA, pack2(q2.z, q2.z), w[10]);
            ffma2(eB, pack2(q2.w, q2.w), w[11]);
            ffma2(eA, pack2(q3.x, q3.x), w[12]);
            ffma2(eB, pack2(q3.y, q3.y), w[13]);
            ffma2(eA, pack2(q3.z, q3.z), w[14]);
            ffma2(eB, pack2(q3.w, q3.w), w[15]);
            ull es = add2(eA, eB);
            float m0, m1;
            unpack2(es, m0, m1);
            a0 += fmaxf(m0, 0.f);
            a1 += fmaxf(m1, 0.f);
        }
        float2 xs = *(const float2*)(x + (size_t)n * 64 + lane * 2);
        float h0 = fmaf(epsv, xs.x, a0);
        float h1 = fmaf(epsv, xs.y, a1);
        *(ulonglong2*)&hdup[wib][j][2 * lane] =
            make_ulonglong2(pack2(h0, h0), pack2(h1, h1));
    }
    __syncwarp();

    const ull b1p = pack2(b1[lane * 2], b1[lane * 2 + 1]);
    const ull b2p = pack2(b2[lane * 2], b2[lane * 2 + 1]);

    // ---- MLP matmul 1 ----
    ull acc[4] = {b1p, b1p, b1p, b1p};
#pragma unroll 8
    for (int kk = 0; kk < 32; kk++) {
        ulonglong2 wv = W1v[kk * 32 + lane];
#pragma unroll
        for (int j = 0; j < 4; j++) {
            ulonglong2 a = *(const ulonglong2*)&hdup[wib][j][2 * kk];
            ffma2(acc[j], a.x, wv.x);
            ffma2(acc[j], a.y, wv.y);
        }
    }
    __syncwarp();
#pragma unroll
    for (int j = 0; j < 4; j++) {
        float y0, y1;
        unpack2(acc[j], y0, y1);
        y0 = fmaxf(y0, 0.f);
        y1 = fmaxf(y1, 0.f);
        *(ulonglong2*)&hdup[wib][j][2 * lane] =
            make_ulonglong2(pack2(y0, y0), pack2(y1, y1));
        acc[j] = b2p;
    }
    __syncwarp();

    // ---- MLP matmul 2 ----
#pragma unroll 8
    for (int kk = 0; kk < 32; kk++) {
        ulonglong2 wv = W2v[kk * 32 + lane];
#pragma unroll
        for (int j = 0; j < 4; j++) {
            ulonglong2 a = *(const ulonglong2*)&hdup[wib][j][2 * kk];
            ffma2(acc[j], a.x, wv.x);
            ffma2(acc[j], a.y, wv.y);
        }
    }

#pragma unroll
    for (int j = 0; j < 4; j++) {
        float y0, y1;
        unpack2(acc[j], y0, y1);
        y0 = fmaxf(y0, 0.f);
        y1 = fmaxf(y1, 0.f);
        if (!LAST) {
            *(float2*)(xout + (size_t)(n0 + j) * 64 + lane * 2) = make_float2(y0, y1);
        } else {
            int g = batch[n0 + j];
            red2(sums + (size_t)g * 64 + lane * 2, y0, y1);
            if (lane == 0) atomicAdd(cnts + g, 1.0f);
        }
    }
}

// ============================ head ==========================================
__global__ void __launch_bounds__(256) head_kernel(
    const float* __restrict__ sums, const float* __restrict__ cnts,
    const float* __restrict__ t_cond,
    const float* __restrict__ hW1, const float* __restrict__ hb1,
    const float* __restrict__ hW2, const float* __restrict__ hb2,
    float* __restrict__ out)
{
    const int lane = threadIdx.x & 31;
    const int g    = (blockIdx.x * blockDim.x + threadIdx.x) >> 5;
    if (g >= GG) return;

    float c  = fmaxf(cnts[g], 1.0f);
    float p0 = sums[(size_t)g * 64 + lane] / c;
    float p1 = sums[(size_t)g * 64 + lane + 32] / c;

    float acc0 = hb1[lane], acc1 = hb1[lane + 32];
    for (int k = 0; k < 32; k++) {
        float a = __shfl_sync(0xFFFFFFFFu, p0, k);
        acc0 = fmaf(a, hW1[k * 64 + lane],      acc0);
        acc1 = fmaf(a, hW1[k * 64 + lane + 32], acc1);
    }
    for (int k = 0; k < 32; k++) {
        float a = __shfl_sync(0xFFFFFFFFu, p1, k);
        acc0 = fmaf(a, hW1[(k + 32) * 64 + lane],      acc0);
        acc1 = fmaf(a, hW1[(k + 32) * 64 + lane + 32], acc1);
    }
    float t = t_cond[g];
    acc0 = fmaf(t, hW1[64 * 64 + lane],      acc0);
    acc1 = fmaf(t, hW1[64 * 64 + lane + 32], acc1);

    acc0 = fmaxf(acc0, 0.f);
    acc1 = fmaxf(acc1, 0.f);

    float r = acc0 * hW2[lane] + acc1 * hW2[lane + 32];
#pragma unroll
    for (int o = 16; o; o >>= 1) r += __shfl_xor_sync(0xFFFFFFFFu, r, o);
    if (lane == 0) out[g] = r + hb2[0];
}

// Trailing cleanup: re-zero accumulators so the NEXT execution starts clean.
// (Device globals are zero-initialized at module load, covering the first call.)
__global__ void __launch_bounds__(256) cleanup_kernel(int* __restrict__ cnt,
                                                      float* __restrict__ sums,
                                                      float* __restrict__ cnts) {
    int i = blockIdx.x * blockDim.x + threadIdx.x;
    if (i < NN) cnt[i] = 0;
    if (i < GG * 64) sums[i] = 0.f;
    if (i < GG) cnts[i] = 0.f;
}

// ============================================================================
extern "C" void kernel_launch(void* const* d_in, const int* in_sizes, int n_in,
                              void* d_out, int out_size)
{
    const float* x      = (const float*)d_in[0];
    const int*   ei     = (const int*)  d_in[1];
    const float* ea     = (const float*)d_in[2];
    const int*   batch  = (const int*)  d_in[3];
    const float* t_cond = (const float*)d_in[4];
    const float* lin_e  = (const float*)d_in[5];
    const float* W1     = (const float*)d_in[6];
    const float* b1     = (const float*)d_in[7];
    const float* W2     = (const float*)d_in[8];
    const float* b2     = (const float*)d_in[9];
    const float* eps    = (const float*)d_in[10];
    const float* hW1    = (const float*)d_in[11];
    const float* hb1    = (const float*)d_in[12];
    const float* hW2    = (const float*)d_in[13];
    const float* hb2    = (const float*)d_in[14];
    float* out = (float*)d_out;

    float *buf0, *buf1, *eaperm, *sums, *cnts;
    int *rowptr, *cnt, *cursor, *srcperm;
    cudaGetSymbolAddress((void**)&buf0, g_buf0);
    cudaGetSymbolAddress((void**)&buf1, g_buf1);
    cudaGetSymbolAddress((void**)&rowptr, g_rowptr);
    cudaGetSymbolAddress((void**)&cnt, g_cnt);
    cudaGetSymbolAddress((void**)&cursor, g_cursor);
    cudaGetSymbolAddress((void**)&srcperm, g_srcperm);
    cudaGetSymbolAddress((void**)&eaperm, g_eaperm);
    cudaGetSymbolAddress((void**)&sums, g_sums);
    cudaGetSymbolAddress((void**)&cnts, g_cnts);

    // ---- CSR build (3 kernels, no memsets) ----
    count_kernel<<<(EE + 255) / 256, 256>>>(ei, cnt);                        // 1
    scan_kernel<<<1, 1024>>>(cnt, rowptr, cursor);                           // 2
    scatter_kernel<<<(EE + 255) / 256, 256>>>(ei, ea, cursor, srcperm, eaperm); // 3

    // ---- 4 fused layers (launches 4..7 -> ncu capture hits a layer) ----
    const int blocks = NN / 4 / 8;  // 3125
    float* bufs[2] = {buf0, buf1};
    const float* cur = x;
    for (int l = 0; l < 3; l++) {
        float* nxt = bufs[l & 1];
        layer_kernel<false><<<blocks, 256>>>(
            cur, rowptr, srcperm, eaperm,
            lin_e + (size_t)l * 16 * 64,
            W1 + (size_t)l * 64 * 64, b1 + (size_t)l * 64,
            W2 + (size_t)l * 64 * 64, b2 + (size_t)l * 64,
            eps, l, nxt, batch, sums, cnts);
        cur = nxt;
    }
    layer_kernel<true><<<blocks, 256>>>(
        cur, rowptr, srcperm, eaperm,
        lin_e + (size_t)3 * 16 * 64,
        W1 + (size_t)3 * 64 * 64, b1 + (size_t)3 * 64,
        W2 + (size_t)3 * 64 * 64, b2 + (size_t)3 * 64,
        eps, 3, nullptr, batch, sums, cnts);

    head_kernel<<<(GG + 7) / 8, 256>>>(sums, cnts, t_cond, hW1, hb1, hW2, hb2, out); // 8
    cleanup_kernel<<<(GG * 64 + 255) / 256, 256>>>(cnt, sums, cnts);                 // 9
}

// round 5
// speedup vs baseline: 1.3019x; 1.2570x over previous
#include <cuda_runtime.h>

#define NN 100000
#define EE 1000000
#define GG 2000

// ---------------- scratch (device globals; no allocation allowed) ----------
__device__ float g_buf0[NN * 64];
__device__ float g_buf1[NN * 64];
__device__ int   g_rowptr[NN + 1];
__device__ int   g_cnt[NN];       // zero-init at load; cleanup re-zeros
__device__ int   g_cursor[NN];
__device__ int   g_srcperm[EE];
__device__ float g_eaperm[EE * 16];
__device__ float g_sums[GG * 64]; // zero-init at load; cleanup re-zeros
__device__ float g_cnts[GG];      // zero-init at load; cleanup re-zeros

typedef unsigned long long ull;

__device__ __forceinline__ ull pack2(float a, float b) {
    ull r; asm("mov.b64 %0, {%1,%2};" : "=l"(r) : "f"(a), "f"(b)); return r;
}
__device__ __forceinline__ void unpack2(ull v, float& a, float& b) {
    asm("mov.b64 {%0,%1}, %2;" : "=f"(a), "=f"(b) : "l"(v));
}
__device__ __forceinline__ void ffma2(ull& d, ull a, ull b) {
    asm("fma.rn.f32x2 %0, %1, %2, %0;" : "+l"(d) : "l"(a), "l"(b));
}
__device__ __forceinline__ void red2(float* p, float x, float y) {
    asm volatile("red.global.add.v2.f32 [%0], {%1,%2};"
                 :: "l"(p), "f"(x), "f"(y) : "memory");
}

// ============================ CSR build =====================================
__global__ void __launch_bounds__(256) count_kernel(const int* __restrict__ ei,
                                                    int* __restrict__ cnt) {
    int e = blockIdx.x * blockDim.x + threadIdx.x;
    if (e < EE) atomicAdd(&cnt[ei[EE + e]], 1);
}

__global__ void __launch_bounds__(1024) scan_kernel(const int* __restrict__ cnt,
                                                    int* __restrict__ rowptr,
                                                    int* __restrict__ cursor) {
    const int CH = 100;
    int tid = threadIdx.x;
    int base = tid * CH;
    int s = 0;
    for (int i = 0; i < CH; i += 4) {
        int idx = base + i;
        if (idx + 3 < NN) {
            int4 v = *(const int4*)(cnt + idx);
            s += v.x + v.y + v.z + v.w;
        } else {
            for (int t = 0; t < 4; t++)
                if (idx + t < NN) s += cnt[idx + t];
        }
    }
    __shared__ int sh[1024];
    sh[tid] = s;
    __syncthreads();
    for (int off = 1; off < 1024; off <<= 1) {
        int v = (tid >= off) ? sh[tid - off] : 0;
        __syncthreads();
        sh[tid] += v;
        __syncthreads();
    }
    int run = sh[tid] - s;
    for (int i = 0; i < CH; i++) {
        int idx = base + i;
        if (idx < NN) {
            rowptr[idx] = run;
            cursor[idx] = run;
            run += cnt[idx];
        }
    }
    if (NN >= base && NN < base + CH) rowptr[NN] = run;
}

__global__ void __launch_bounds__(256) scatter_kernel(const int* __restrict__ ei,
                                                      const float* __restrict__ ea,
                                                      int* __restrict__ cursor,
                                                      int* __restrict__ srcperm,
                                                      float* __restrict__ eaperm) {
    int e = blockIdx.x * blockDim.x + threadIdx.x;
    if (e < EE) {
        int d = ei[EE + e];
        int pos = atomicAdd(&cursor[d], 1);
        srcperm[pos] = ei[e];
        const float4* src = (const float4*)(ea + (size_t)e * 16);
        float4* dst = (float4*)(eaperm + (size_t)pos * 16);
        float4 v0 = src[0], v1 = src[1], v2 = src[2], v3 = src[3];
        dst[0] = v0; dst[1] = v1; dst[2] = v2; dst[3] = v3;
    }
}

// ============================ fused layer ===================================
// Lane owns dims (2*lane, 2*lane+1). Warp handles 4 nodes (contiguous CSR range).
// Edge phase: 8-edge chunks; eaperm staged coalesced into shared, 8 x-gathers
// issued back-to-back into registers. Pair-accumulation (k,k+1) avoids all
// operand-duplication movs; horizontal add folded into the epilogue.
template <bool LAST>
__global__ void __launch_bounds__(256, 3) layer_kernel(
    const float* __restrict__ x,
    const int* __restrict__ rowptr, const int* __restrict__ srcperm,
    const float* __restrict__ eaperm,
    const float* __restrict__ line,
    const float* __restrict__ W1, const float* __restrict__ b1,
    const float* __restrict__ W2, const float* __restrict__ b2,
    const float* __restrict__ epsp, int l,
    float* __restrict__ xout,
    const int* __restrict__ batch,
    float* __restrict__ sums, float* __restrict__ cnts)
{
    // Wv[kk][lane] = { (W[2kk][2l], W[2kk+1][2l]), (W[2kk][2l+1], W[2kk+1][2l+1]) }
    __shared__ ulonglong2 W1v[32 * 32];   // 16 KB
    __shared__ ulonglong2 W2v[32 * 32];   // 16 KB
    __shared__ ull hdup[8][4][32];        //  8 KB : (h[2k], h[2k+1]) pairs
    __shared__ ulonglong2 easm[8][32];    //  4 KB : 8 edges x 64B per warp

    for (int i = threadIdx.x; i < 32 * 32; i += 256) {
        int kk = i >> 5, ln = i & 31;
        W1v[i] = make_ulonglong2(
            pack2(W1[(2 * kk) * 64 + 2 * ln],     W1[(2 * kk + 1) * 64 + 2 * ln]),
            pack2(W1[(2 * kk) * 64 + 2 * ln + 1], W1[(2 * kk + 1) * 64 + 2 * ln + 1]));
        W2v[i] = make_ulonglong2(
            pack2(W2[(2 * kk) * 64 + 2 * ln],     W2[(2 * kk + 1) * 64 + 2 * ln]),
            pack2(W2[(2 * kk) * 64 + 2 * ln + 1], W2[(2 * kk + 1) * 64 + 2 * ln + 1]));
    }
    __syncthreads();

    const int lane = threadIdx.x & 31;
    const int wib  = threadIdx.x >> 5;

    // Edge weights as k-pairs: wP for dim 2*lane, wQ for dim 2*lane+1.
    ull wP[8], wQ[8];
#pragma unroll
    for (int k = 0; k < 8; k++) {
        wP[k] = pack2(line[(2 * k) * 64 + 2 * lane],     line[(2 * k + 1) * 64 + 2 * lane]);
        wQ[k] = pack2(line[(2 * k) * 64 + 2 * lane + 1], line[(2 * k + 1) * 64 + 2 * lane + 1]);
    }

    const float epsv = 1.0f + epsp[l];
    const int warp = (blockIdx.x * 256 + threadIdx.x) >> 5;
    const int n0 = warp * 4;  // grid sized exactly

    const int r0   = rowptr[n0];
    const int bnd1 = rowptr[n0 + 1];
    const int bnd2 = rowptr[n0 + 2];
    const int bnd3 = rowptr[n0 + 3];
    const int r4   = rowptr[n0 + 4];

    float4* easm4 = (float4*)&easm[wib][0];
    const float4* eaperm4 = (const float4*)eaperm;

    int j = 0;
    int bnext = bnd1;
    float a0 = 0.f, a1 = 0.f;

    for (int cb = r0; cb < r4; cb += 8) {
        const int cnt = min(8, r4 - cb);

        // stage edge features: cnt*4 float4s, coalesced
        if (lane < cnt * 4)
            easm4[lane] = __ldg(&eaperm4[(size_t)cb * 4 + lane]);

        // stage src indices + fire all gathers back-to-back
        int sreg = (lane < cnt) ? __ldg(srcperm + cb + lane) : 0;
        float2 xv[8];
#pragma unroll
        for (int t = 0; t < 8; t++) {
            int st = __shfl_sync(0xFFFFFFFFu, sreg, t);
            if (t < cnt)
                xv[t] = __ldg((const float2*)(x + (size_t)st * 64 + lane * 2));
        }
        __syncwarp();

#pragma unroll
        for (int t = 0; t < 8; t++) {
            if (t >= cnt) break;                 // warp-uniform
            const int p = cb + t;
            while (p >= bnext) {                 // warp-uniform, rare
                float2 xs = *(const float2*)(x + (size_t)(n0 + j) * 64 + lane * 2);
                hdup[wib][j][lane] = pack2(fmaf(epsv, xs.x, a0), fmaf(epsv, xs.y, a1));
                a0 = 0.f; a1 = 0.f;
                j++;
                bnext = (j == 1) ? bnd2 : (j == 2) ? bnd3 : r4;
            }
            ulonglong2 E0 = easm[wib][4 * t + 0];
            ulonglong2 E1 = easm[wib][4 * t + 1];
            ulonglong2 E2 = easm[wib][4 * t + 2];
            ulonglong2 E3 = easm[wib][4 * t + 3];
            ull acP = pack2(0.f, 0.f), acQ = pack2(0.f, 0.f);
            ffma2(acP, E0.x, wP[0]); ffma2(acQ, E0.x, wQ[0]);
            ffma2(acP, E0.y, wP[1]); ffma2(acQ, E0.y, wQ[1]);
            ffma2(acP, E1.x, wP[2]); ffma2(acQ, E1.x, wQ[2]);
            ffma2(acP, E1.y, wP[3]); ffma2(acQ, E1.y, wQ[3]);
            ffma2(acP, E2.x, wP[4]); ffma2(acQ, E2.x, wQ[4]);
            ffma2(acP, E2.y, wP[5]); ffma2(acQ, E2.y, wQ[5]);
            ffma2(acP, E3.x, wP[6]); ffma2(acQ, E3.x, wQ[6]);
            ffma2(acP, E3.y, wP[7]); ffma2(acQ, E3.y, wQ[7]);
            float pa, pb, qa, qb;
            unpack2(acP, pa, pb);
            unpack2(acQ, qa, qb);
            float m0 = (pa + xv[t].x) + pb;
            float m1 = (qa + xv[t].y) + qb;
            a0 += fmaxf(m0, 0.f);
            a1 += fmaxf(m1, 0.f);
        }
        __syncwarp();   // staged buffer reused next chunk
    }
    while (j < 4) {   // flush remaining nodes (incl. zero-degree)
        float2 xs = *(const float2*)(x + (size_t)(n0 + j) * 64 + lane * 2);
        hdup[wib][j][lane] = pack2(fmaf(epsv, xs.x, a0), fmaf(epsv, xs.y, a1));
        a0 = 0.f; a1 = 0.f;
        j++;
    }
    __syncwarp();

    const float b1v0 = b1[2 * lane], b1v1 = b1[2 * lane + 1];
    const float b2v0 = b2[2 * lane], b2v1 = b2[2 * lane + 1];

    // ---- MLP matmul 1 (bias folded into acc.lo) ----
    ull accP[4], accQ[4];
#pragma unroll
    for (int jj = 0; jj < 4; jj++) {
        accP[jj] = pack2(b1v0, 0.f);
        accQ[jj] = pack2(b1v1, 0.f);
    }
#pragma unroll 8
    for (int kk = 0; kk < 32; kk++) {
        ulonglong2 wv = W1v[kk * 32 + lane];
#pragma unroll
        for (int jj = 0; jj < 4; jj++) {
            ull hp = hdup[wib][jj][kk];
            ffma2(accP[jj], hp, wv.x);
            ffma2(accQ[jj], hp, wv.y);
        }
    }
    __syncwarp();
#pragma unroll
    for (int jj = 0; jj < 4; jj++) {
        float pa, pb, qa, qb;
        unpack2(accP[jj], pa, pb);
        unpack2(accQ[jj], qa, qb);
        float y0 = fmaxf(pa + pb, 0.f);
        float y1 = fmaxf(qa + qb, 0.f);
        hdup[wib][jj][lane] = pack2(y0, y1);
        accP[jj] = pack2(b2v0, 0.f);
        accQ[jj] = pack2(b2v1, 0.f);
    }
    __syncwarp();

    // ---- MLP matmul 2 ----
#pragma unroll 8
    for (int kk = 0; kk < 32; kk++) {
        ulonglong2 wv = W2v[kk * 32 + lane];
#pragma unroll
        for (int jj = 0; jj < 4; jj++) {
            ull hp = hdup[wib][jj][kk];
            ffma2(accP[jj], hp, wv.x);
            ffma2(accQ[jj], hp, wv.y);
        }
    }

#pragma unroll
    for (int jj = 0; jj < 4; jj++) {
        float pa, pb, qa, qb;
        unpack2(accP[jj], pa, pb);
        unpack2(accQ[jj], qa, qb);
        float y0 = fmaxf(pa + pb, 0.f);
        float y1 = fmaxf(qa + qb, 0.f);
        if (!LAST) {
            *(float2*)(xout + (size_t)(n0 + jj) * 64 + lane * 2) = make_float2(y0, y1);
        } else {
            int g = batch[n0 + jj];
            red2(sums + (size_t)g * 64 + lane * 2, y0, y1);
            if (lane == 0) atomicAdd(cnts + g, 1.0f);
        }
    }
}

// ============================ head ==========================================
__global__ void __launch_bounds__(256) head_kernel(
    const float* __restrict__ sums, const float* __restrict__ cnts,
    const float* __restrict__ t_cond,
    const float* __restrict__ hW1, const float* __restrict__ hb1,
    const float* __restrict__ hW2, const float* __restrict__ hb2,
    float* __restrict__ out)
{
    const int lane = threadIdx.x & 31;
    const int g    = (blockIdx.x * blockDim.x + threadIdx.x) >> 5;
    if (g >= GG) return;

    float c  = fmaxf(cnts[g], 1.0f);
    float p0 = sums[(size_t)g * 64 + lane] / c;
    float p1 = sums[(size_t)g * 64 + lane + 32] / c;

    float acc0 = hb1[lane], acc1 = hb1[lane + 32];
    for (int k = 0; k < 32; k++) {
        float a = __shfl_sync(0xFFFFFFFFu, p0, k);
        acc0 = fmaf(a, hW1[k * 64 + lane],      acc0);
        acc1 = fmaf(a, hW1[k * 64 + lane + 32], acc1);
    }
    for (int k = 0; k < 32; k++) {
        float a = __shfl_sync(0xFFFFFFFFu, p1, k);
        acc0 = fmaf(a, hW1[(k + 32) * 64 + lane],      acc0);
        acc1 = fmaf(a, hW1[(k + 32) * 64 + lane + 32], acc1);
    }
    float t = t_cond[g];
    acc0 = fmaf(t, hW1[64 * 64 + lane],      acc0);
    acc1 = fmaf(t, hW1[64 * 64 + lane + 32], acc1);

    acc0 = fmaxf(acc0, 0.f);
    acc1 = fmaxf(acc1, 0.f);

    float r = acc0 * hW2[lane] + acc1 * hW2[lane + 32];
#pragma unroll
    for (int o = 16; o; o >>= 1) r += __shfl_xor_sync(0xFFFFFFFFu, r, o);
    if (lane == 0) out[g] = r + hb2[0];
}

// Trailing cleanup: re-zero accumulators for the next execution.
__global__ void __launch_bounds__(256) cleanup_kernel(int* __restrict__ cnt,
                                                      float* __restrict__ sums,
                                                      float* __restrict__ cnts) {
    int i = blockIdx.x * blockDim.x + threadIdx.x;
    if (i < NN) cnt[i] = 0;
    if (i < GG * 64) sums[i] = 0.f;
    if (i < GG) cnts[i] = 0.f;
}

// ============================================================================
extern "C" void kernel_launch(void* const* d_in, const int* in_sizes, int n_in,
                              void* d_out, int out_size)
{
    const float* x      = (const float*)d_in[0];
    const int*   ei     = (const int*)  d_in[1];
    const float* ea     = (const float*)d_in[2];
    const int*   batch  = (const int*)  d_in[3];
    const float* t_cond = (const float*)d_in[4];
    const float* lin_e  = (const float*)d_in[5];
    const float* W1     = (const float*)d_in[6];
    const float* b1     = (const float*)d_in[7];
    const float* W2     = (const float*)d_in[8];
    const float* b2     = (const float*)d_in[9];
    const float* eps    = (const float*)d_in[10];
    const float* hW1    = (const float*)d_in[11];
    const float* hb1    = (const float*)d_in[12];
    const float* hW2    = (const float*)d_in[13];
    const float* hb2    = (const float*)d_in[14];
    float* out = (float*)d_out;

    float *buf0, *buf1, *eaperm, *sums, *cnts;
    int *rowptr, *cnt, *cursor, *srcperm;
    cudaGetSymbolAddress((void**)&buf0, g_buf0);
    cudaGetSymbolAddress((void**)&buf1, g_buf1);
    cudaGetSymbolAddress((void**)&rowptr, g_rowptr);
    cudaGetSymbolAddress((void**)&cnt, g_cnt);
    cudaGetSymbolAddress((void**)&cursor, g_cursor);
    cudaGetSymbolAddress((void**)&srcperm, g_srcperm);
    cudaGetSymbolAddress((void**)&eaperm, g_eaperm);
    cudaGetSymbolAddress((void**)&sums, g_sums);
    cudaGetSymbolAddress((void**)&cnts, g_cnts);

    // ---- CSR build ----
    count_kernel<<<(EE + 255) / 256, 256>>>(ei, cnt);
    scan_kernel<<<1, 1024>>>(cnt, rowptr, cursor);
    scatter_kernel<<<(EE + 255) / 256, 256>>>(ei, ea, cursor, srcperm, eaperm);

    // ---- 4 fused layers ----
    const int blocks = NN / 4 / 8;  // 3125
    float* bufs[2] = {buf0, buf1};
    const float* cur = x;
    for (int l = 0; l < 3; l++) {
        float* nxt = bufs[l & 1];
        layer_kernel<false><<<blocks, 256>>>(
            cur, rowptr, srcperm, eaperm,
            lin_e + (size_t)l * 16 * 64,
            W1 + (size_t)l * 64 * 64, b1 + (size_t)l * 64,
            W2 + (size_t)l * 64 * 64, b2 + (size_t)l * 64,
            eps, l, nxt, batch, sums, cnts);
        cur = nxt;
    }
    layer_kernel<true><<<blocks, 256>>>(
        cur, rowptr, srcperm, eaperm,
        lin_e + (size_t)3 * 16 * 64,
        W1 + (size_t)3 * 64 * 64, b1 + (size_t)3 * 64,
        W2 + (size_t)3 * 64 * 64, b2 + (size_t)3 * 64,
        eps, 3, nullptr, batch, sums, cnts);

    head_kernel<<<(GG + 7) / 8, 256>>>(sums, cnts, t_cond, hW1, hb1, hW2, hb2, out);
    cleanup_kernel<<<(GG * 64 + 255) / 256, 256>>>(cnt, sums, cnts);
}

// round 6
// speedup vs baseline: 1.3801x; 1.0601x over previous
#include <cuda_runtime.h>

#define NN 100000
#define EE 1000000
#define GG 2000

// ---------------- scratch (device globals; no allocation allowed) ----------
__device__ float g_buf0[NN * 64];
__device__ float g_buf1[NN * 64];
__device__ int   g_rowptr[NN + 1];
__device__ int   g_cnt[NN];       // zero-init at load; cleanup re-zeros
__device__ int   g_cursor[NN];
__device__ int   g_srcperm[EE];
__device__ float g_eaperm[EE * 16];
__device__ float g_sums[GG * 64]; // zero-init at load; cleanup re-zeros
__device__ float g_cnts[GG];      // zero-init at load; cleanup re-zeros

typedef unsigned long long ull;

__device__ __forceinline__ ull pack2(float a, float b) {
    ull r; asm("mov.b64 %0, {%1,%2};" : "=l"(r) : "f"(a), "f"(b)); return r;
}
__device__ __forceinline__ void unpack2(ull v, float& a, float& b) {
    asm("mov.b64 {%0,%1}, %2;" : "=f"(a), "=f"(b) : "l"(v));
}
__device__ __forceinline__ void ffma2(ull& d, ull a, ull b) {
    asm("fma.rn.f32x2 %0, %1, %2, %0;" : "+l"(d) : "l"(a), "l"(b));
}
__device__ __forceinline__ void red2(float* p, float x, float y) {
    asm volatile("red.global.add.v2.f32 [%0], {%1,%2};"
                 :: "l"(p), "f"(x), "f"(y) : "memory");
}

// ============================ CSR build =====================================
__global__ void __launch_bounds__(256) count_kernel(const int* __restrict__ ei,
                                                    int* __restrict__ cnt) {
    int e = blockIdx.x * blockDim.x + threadIdx.x;
    if (e < EE) atomicAdd(&cnt[ei[EE + e]], 1);
}

__global__ void __launch_bounds__(1024) scan_kernel(const int* __restrict__ cnt,
                                                    int* __restrict__ rowptr,
                                                    int* __restrict__ cursor) {
    const int CH = 100;
    int tid = threadIdx.x;
    int base = tid * CH;
    int s = 0;
    for (int i = 0; i < CH; i += 4) {
        int idx = base + i;
        if (idx + 3 < NN) {
            int4 v = *(const int4*)(cnt + idx);
            s += v.x + v.y + v.z + v.w;
        } else {
            for (int t = 0; t < 4; t++)
                if (idx + t < NN) s += cnt[idx + t];
        }
    }
    __shared__ int sh[1024];
    sh[tid] = s;
    __syncthreads();
    for (int off = 1; off < 1024; off <<= 1) {
        int v = (tid >= off) ? sh[tid - off] : 0;
        __syncthreads();
        sh[tid] += v;
        __syncthreads();
    }
    int run = sh[tid] - s;
    for (int i = 0; i < CH; i += 4) {
        int idx = base + i;
        if (idx + 3 < NN) {
            int4 c = *(const int4*)(cnt + idx);
            int4 rp;
            rp.x = run;
            rp.y = run + c.x;
            rp.z = rp.y + c.y;
            rp.w = rp.z + c.z;
            *(int4*)(rowptr + idx) = rp;
            *(int4*)(cursor + idx) = rp;
            run = rp.w + c.w;
        } else {
            for (int t = 0; t < 4; t++) {
                int k2 = idx + t;
                if (k2 < NN) { rowptr[k2] = run; cursor[k2] = run; run += cnt[k2]; }
            }
        }
    }
    if (NN >= base && NN < base + CH) rowptr[NN] = run;
}

__global__ void __launch_bounds__(256) scatter_kernel(const int* __restrict__ ei,
                                                      const float* __restrict__ ea,
                                                      int* __restrict__ cursor,
                                                      int* __restrict__ srcperm,
                                                      float* __restrict__ eaperm) {
    int e = blockIdx.x * blockDim.x + threadIdx.x;
    if (e < EE) {
        int d = ei[EE + e];
        int pos = atomicAdd(&cursor[d], 1);
        srcperm[pos] = ei[e];
        const float4* src = (const float4*)(ea + (size_t)e * 16);
        float4* dst = (float4*)(eaperm + (size_t)pos * 16);
        float4 v0 = src[0], v1 = src[1], v2 = src[2], v3 = src[3];
        dst[0] = v0; dst[1] = v1; dst[2] = v2; dst[3] = v3;
    }
}

// ============================ fused layer ===================================
// Lane owns dims (2*lane, 2*lane+1). Warp handles 4 nodes (contiguous CSR range).
// Edge phase: 8-edge chunks, software-pipelined one chunk ahead:
//   - edge features LDG'd at iter top into regs, STS'd to the ping-pong shared
//     buffer at iter END (compute hides the LDG latency before the STS waits)
//   - x gathers for the next chunk fired at iter top into regs
//   - srcperm kept TWO chunks ahead so the shfl never waits on its load
template <bool LAST>
__global__ void __launch_bounds__(256, 2) layer_kernel(
    const float* __restrict__ x,
    const int* __restrict__ rowptr, const int* __restrict__ srcperm,
    const float* __restrict__ eaperm,
    const float* __restrict__ line,
    const float* __restrict__ W1, const float* __restrict__ b1,
    const float* __restrict__ W2, const float* __restrict__ b2,
    const float* __restrict__ epsp, int l,
    float* __restrict__ xout,
    const int* __restrict__ batch,
    float* __restrict__ sums, float* __restrict__ cnts)
{
    __shared__ ulonglong2 W1v[32 * 32];      // 16 KB
    __shared__ ulonglong2 W2v[32 * 32];      // 16 KB
    __shared__ ull hd[8][32][4];             //  8 KB : [warp][dim-pair][node]
    __shared__ ulonglong2 easm[8][2][32];    //  8 KB : [warp][buf][8 edges x 4 qwords]

    for (int i = threadIdx.x; i < 32 * 32; i += 256) {
        int kk = i >> 5, ln = i & 31;
        W1v[i] = make_ulonglong2(
            pack2(W1[(2 * kk) * 64 + 2 * ln],     W1[(2 * kk + 1) * 64 + 2 * ln]),
            pack2(W1[(2 * kk) * 64 + 2 * ln + 1], W1[(2 * kk + 1) * 64 + 2 * ln + 1]));
        W2v[i] = make_ulonglong2(
            pack2(W2[(2 * kk) * 64 + 2 * ln],     W2[(2 * kk + 1) * 64 + 2 * ln]),
            pack2(W2[(2 * kk) * 64 + 2 * ln + 1], W2[(2 * kk + 1) * 64 + 2 * ln + 1]));
    }
    __syncthreads();

    const int lane = threadIdx.x & 31;
    const int wib  = threadIdx.x >> 5;

    ull wP[8], wQ[8];
#pragma unroll
    for (int k = 0; k < 8; k++) {
        wP[k] = pack2(line[(2 * k) * 64 + 2 * lane],     line[(2 * k + 1) * 64 + 2 * lane]);
        wQ[k] = pack2(line[(2 * k) * 64 + 2 * lane + 1], line[(2 * k + 1) * 64 + 2 * lane + 1]);
    }

    const float epsv = 1.0f + epsp[l];
    const int warp = (blockIdx.x * 256 + threadIdx.x) >> 5;
    const int n0 = warp * 4;

    const int r0   = rowptr[n0];
    const int bnd1 = rowptr[n0 + 1];
    const int bnd2 = rowptr[n0 + 2];
    const int bnd3 = rowptr[n0 + 3];
    const int r4   = rowptr[n0 + 4];

    const float4* eaperm4 = (const float4*)eaperm;

    int j = 0;
    int bnext = bnd1;
    float a0 = 0.f, a1 = 0.f;

    int cb = r0;
    int cnt = min(8, r4 - cb);
    float2 xv[8];
    int sr_hold = 0;   // srcperm values for chunk cb+8

    if (cnt > 0) {
        // stage chunk 0 directly (one exposed stall per warp)
        if (lane < cnt * 4)
            ((float4*)&easm[wib][0][0])[lane] = __ldg(&eaperm4[(size_t)cb * 4 + lane]);
        int adr0 = cb + lane;
        adr0 = adr0 < r4 ? adr0 : r4 - 1;
        int sr0 = __ldg(srcperm + adr0);
#pragma unroll
        for (int t = 0; t < 8; t++) {
            int st = __shfl_sync(0xFFFFFFFFu, sr0, t);
            if (t < cnt)
                xv[t] = __ldg((const float2*)(x + (size_t)st * 64 + lane * 2));
        }
        int adr1 = cb + 8 + lane;
        adr1 = adr1 < r4 ? adr1 : r4 - 1;
        sr_hold = __ldg(srcperm + adr1);
    }

    int buf = 0;
    while (cnt > 0) {
        const int cb_n = cb + 8;
        const int cnt_n = min(8, r4 - cb_n);

        // ---- prefetch chunk cb_n ----
        float2 xn[8];
        float4 ea_pf;
        const bool pf = (cnt_n > 0) && (lane < cnt_n * 4);
        if (pf) ea_pf = __ldg(&eaperm4[(size_t)cb_n * 4 + lane]);
        if (cnt_n > 0) {
#pragma unroll
            for (int t = 0; t < 8; t++) {
                int st = __shfl_sync(0xFFFFFFFFu, sr_hold, t);
                if (t < cnt_n)
                    xn[t] = __ldg((const float2*)(x + (size_t)st * 64 + lane * 2));
            }
            int adr = cb + 16 + lane;
            adr = adr < r4 ? adr : r4 - 1;
            sr_hold = __ldg(srcperm + adr);
        }

        __syncwarp();   // prev compute reads done; this iter's staged buf visible

        // ---- compute chunk cb from easm[buf] + xv ----
#pragma unroll
        for (int t = 0; t < 8; t++) {
            if (t >= cnt) break;                 // warp-uniform
            const int p = cb + t;
            while (p >= bnext) {                 // warp-uniform, rare
                float2 xs = *(const float2*)(x + (size_t)(n0 + j) * 64 + lane * 2);
                hd[wib][lane][j] = pack2(fmaf(epsv, xs.x, a0), fmaf(epsv, xs.y, a1));
                a0 = 0.f; a1 = 0.f;
                j++;
                bnext = (j == 1) ? bnd2 : (j == 2) ? bnd3 : r4;
            }
            ulonglong2 E0 = easm[wib][buf][4 * t + 0];
            ulonglong2 E1 = easm[wib][buf][4 * t + 1];
            ulonglong2 E2 = easm[wib][buf][4 * t + 2];
            ulonglong2 E3 = easm[wib][buf][4 * t + 3];
            ull acP = pack2(0.f, 0.f), acQ = pack2(0.f, 0.f);
            ffma2(acP, E0.x, wP[0]); ffma2(acQ, E0.x, wQ[0]);
            ffma2(acP, E0.y, wP[1]); ffma2(acQ, E0.y, wQ[1]);
            ffma2(acP, E1.x, wP[2]); ffma2(acQ, E1.x, wQ[2]);
            ffma2(acP, E1.y, wP[3]); ffma2(acQ, E1.y, wQ[3]);
            ffma2(acP, E2.x, wP[4]); ffma2(acQ, E2.x, wQ[4]);
            ffma2(acP, E2.y, wP[5]); ffma2(acQ, E2.y, wQ[5]);
            ffma2(acP, E3.x, wP[6]); ffma2(acQ, E3.x, wQ[6]);
            ffma2(acP, E3.y, wP[7]); ffma2(acQ, E3.y, wQ[7]);
            float pa, pb, qa, qb;
            unpack2(acP, pa, pb);
            unpack2(acQ, qa, qb);
            float m0 = (pa + xv[t].x) + pb;
            float m1 = (qa + xv[t].y) + qb;
            a0 += fmaxf(m0, 0.f);
            a1 += fmaxf(m1, 0.f);
        }

        // deferred STS: LDG latency was hidden by the compute above
        if (pf) ((float4*)&easm[wib][buf ^ 1][0])[lane] = ea_pf;

#pragma unroll
        for (int t = 0; t < 8; t++) xv[t] = xn[t];

        buf ^= 1;
        cb = cb_n;
        cnt = cnt_n;
    }
    while (j < 4) {   // flush remaining nodes (incl. zero-degree)
        float2 xs = *(const float2*)(x + (size_t)(n0 + j) * 64 + lane * 2);
        hd[wib][lane][j] = pack2(fmaf(epsv, xs.x, a0), fmaf(epsv, xs.y, a1));
        a0 = 0.f; a1 = 0.f;
        j++;
    }
    __syncwarp();

    const float b1v0 = b1[2 * lane], b1v1 = b1[2 * lane + 1];
    const float b2v0 = b2[2 * lane], b2v1 = b2[2 * lane + 1];

    // ---- MLP matmul 1 (bias folded into acc.lo) ----
    ull accP[4], accQ[4];
#pragma unroll
    for (int jj = 0; jj < 4; jj++) {
        accP[jj] = pack2(b1v0, 0.f);
        accQ[jj] = pack2(b1v1, 0.f);
    }
#pragma unroll 8
    for (int kk = 0; kk < 32; kk++) {
        ulonglong2 wv  = W1v[kk * 32 + lane];
        ulonglong2 h01 = *(const ulonglong2*)&hd[wib][kk][0];
        ulonglong2 h23 = *(const ulonglong2*)&hd[wib][kk][2];
        ffma2(accP[0], h01.x, wv.x); ffma2(accQ[0], h01.x, wv.y);
        ffma2(accP[1], h01.y, wv.x); ffma2(accQ[1], h01.y, wv.y);
        ffma2(accP[2], h23.x, wv.x); ffma2(accQ[2], h23.x, wv.y);
        ffma2(accP[3], h23.y, wv.x); ffma2(accQ[3], h23.y, wv.y);
    }
    __syncwarp();
    {
        ull y01[4];
#pragma unroll
        for (int jj = 0; jj < 4; jj++) {
            float pa, pb, qa, qb;
            unpack2(accP[jj], pa, pb);
            unpack2(accQ[jj], qa, qb);
            y01[jj] = pack2(fmaxf(pa + pb, 0.f), fmaxf(qa + qb, 0.f));
            accP[jj] = pack2(b2v0, 0.f);
            accQ[jj] = pack2(b2v1, 0.f);
        }
        *(ulonglong2*)&hd[wib][lane][0] = make_ulonglong2(y01[0], y01[1]);
        *(ulonglong2*)&hd[wib][lane][2] = make_ulonglong2(y01[2], y01[3]);
    }
    __syncwarp();

    // ---- MLP matmul 2 ----
#pragma unroll 8
    for (int kk = 0; kk < 32; kk++) {
        ulonglong2 wv  = W2v[kk * 32 + lane];
        ulonglong2 h01 = *(const ulonglong2*)&hd[wib][kk][0];
        ulonglong2 h23 = *(const ulonglong2*)&hd[wib][kk][2];
        ffma2(accP[0], h01.x, wv.x); ffma2(accQ[0], h01.x, wv.y);
        ffma2(accP[1], h01.y, wv.x); ffma2(accQ[1], h01.y, wv.y);
        ffma2(accP[2], h23.x, wv.x); ffma2(accQ[2], h23.x, wv.y);
        ffma2(accP[3], h23.y, wv.x); ffma2(accQ[3], h23.y, wv.y);
    }

#pragma unroll
    for (int jj = 0; jj < 4; jj++) {
        float pa, pb, qa, qb;
        unpack2(accP[jj], pa, pb);
        unpack2(accQ[jj], qa, qb);
        float y0 = fmaxf(pa + pb, 0.f);
        float y1 = fmaxf(qa + qb, 0.f);
        if (!LAST) {
            *(float2*)(xout + (size_t)(n0 + jj) * 64 + lane * 2) = make_float2(y0, y1);
        } else {
            int g = batch[n0 + jj];
            red2(sums + (size_t)g * 64 + lane * 2, y0, y1);
            if (lane == 0) atomicAdd(cnts + g, 1.0f);
        }
    }
}

// ============================ head ==========================================
__global__ void __launch_bounds__(256) head_kernel(
    const float* __restrict__ sums, const float* __restrict__ cnts,
    const float* __restrict__ t_cond,
    const float* __restrict__ hW1, const float* __restrict__ hb1,
    const float* __restrict__ hW2, const float* __restrict__ hb2,
    float* __restrict__ out)
{
    const int lane = threadIdx.x & 31;
    const int g    = (blockIdx.x * blockDim.x + threadIdx.x) >> 5;
    if (g >= GG) return;

    float c  = fmaxf(cnts[g], 1.0f);
    float p0 = sums[(size_t)g * 64 + lane] / c;
    float p1 = sums[(size_t)g * 64 + lane + 32] / c;

    float acc0 = hb1[lane], acc1 = hb1[lane + 32];
    for (int k = 0; k < 32; k++) {
        float a = __shfl_sync(0xFFFFFFFFu, p0, k);
        acc0 = fmaf(a, hW1[k * 64 + lane],      acc0);
        acc1 = fmaf(a, hW1[k * 64 + lane + 32], acc1);
    }
    for (int k = 0; k < 32; k++) {
        float a = __shfl_sync(0xFFFFFFFFu, p1, k);
        acc0 = fmaf(a, hW1[(k + 32) * 64 + lane],      acc0);
        acc1 = fmaf(a, hW1[(k + 32) * 64 + lane + 32], acc1);
    }
    float t = t_cond[g];
    acc0 = fmaf(t, hW1[64 * 64 + lane],      acc0);
    acc1 = fmaf(t, hW1[64 * 64 + lane + 32], acc1);

    acc0 = fmaxf(acc0, 0.f);
    acc1 = fmaxf(acc1, 0.f);

    float r = acc0 * hW2[lane] + acc1 * hW2[lane + 32];
#pragma unroll
    for (int o = 16; o; o >>= 1) r += __shfl_xor_sync(0xFFFFFFFFu, r, o);
    if (lane == 0) out[g] = r + hb2[0];
}

// Trailing cleanup: re-zero accumulators for the next execution.
__global__ void __launch_bounds__(256) cleanup_kernel(int* __restrict__ cnt,
                                                      float* __restrict__ sums,
                                                      float* __restrict__ cnts) {
    int i = blockIdx.x * blockDim.x + threadIdx.x;
    if (i < NN) cnt[i] = 0;
    if (i < GG * 64) sums[i] = 0.f;
    if (i < GG) cnts[i] = 0.f;
}

// ============================================================================
extern "C" void kernel_launch(void* const* d_in, const int* in_sizes, int n_in,
                              void* d_out, int out_size)
{
    const float* x      = (const float*)d_in[0];
    const int*   ei     = (const int*)  d_in[1];
    const float* ea     = (const float*)d_in[2];
    const int*   batch  = (const int*)  d_in[3];
    const float* t_cond = (const float*)d_in[4];
    const float* lin_e  = (const float*)d_in[5];
    const float* W1     = (const float*)d_in[6];
    const float* b1     = (const float*)d_in[7];
    const float* W2     = (const float*)d_in[8];
    const float* b2     = (const float*)d_in[9];
    const float* eps    = (const float*)d_in[10];
    const float* hW1    = (const float*)d_in[11];
    const float* hb1    = (const float*)d_in[12];
    const float* hW2    = (const float*)d_in[13];
    const float* hb2    = (const float*)d_in[14];
    float* out = (float*)d_out;

    float *buf0, *buf1, *eaperm, *sums, *cnts;
    int *rowptr, *cnt, *cursor, *srcperm;
    cudaGetSymbolAddress((void**)&buf0, g_buf0);
    cudaGetSymbolAddress((void**)&buf1, g_buf1);
    cudaGetSymbolAddress((void**)&rowptr, g_rowptr);
    cudaGetSymbolAddress((void**)&cnt, g_cnt);
    cudaGetSymbolAddress((void**)&cursor, g_cursor);
    cudaGetSymbolAddress((void**)&srcperm, g_srcperm);
    cudaGetSymbolAddress((void**)&eaperm, g_eaperm);
    cudaGetSymbolAddress((void**)&sums, g_sums);
    cudaGetSymbolAddress((void**)&cnts, g_cnts);

    // ---- CSR build ----
    count_kernel<<<(EE + 255) / 256, 256>>>(ei, cnt);
    scan_kernel<<<1, 1024>>>(cnt, rowptr, cursor);
    scatter_kernel<<<(EE + 255) / 256, 256>>>(ei, ea, cursor, srcperm, eaperm);

    // ---- 4 fused layers ----
    const int blocks = NN / 4 / 8;  // 3125
    float* bufs[2] = {buf0, buf1};
    const float* cur = x;
    for (int l = 0; l < 3; l++) {
        float* nxt = bufs[l & 1];
        layer_kernel<false><<<blocks, 256>>>(
            cur, rowptr, srcperm, eaperm,
            lin_e + (size_t)l * 16 * 64,
            W1 + (size_t)l * 64 * 64, b1 + (size_t)l * 64,
            W2 + (size_t)l * 64 * 64, b2 + (size_t)l * 64,
            eps, l, nxt, batch, sums, cnts);
        cur = nxt;
    }
    layer_kernel<true><<<blocks, 256>>>(
        cur, rowptr, srcperm, eaperm,
        lin_e + (size_t)3 * 16 * 64,
        W1 + (size_t)3 * 64 * 64, b1 + (size_t)3 * 64,
        W2 + (size_t)3 * 64 * 64, b2 + (size_t)3 * 64,
        eps, 3, nullptr, batch, sums, cnts);

    head_kernel<<<(GG + 7) / 8, 256>>>(sums, cnts, t_cond, hW1, hb1, hW2, hb2, out);
    cleanup_kernel<<<(GG * 64 + 255) / 256, 256>>>(cnt, sums, cnts);
}